// round 1
// baseline (speedup 1.0000x reference)
#include <cuda_runtime.h>

#define TILE_X 128
#define OUT_Y  16
#define HALO   8
#define SM_W   (TILE_X + HALO)   // 136
#define SM_H   (OUT_Y + HALO)    // 24
#define IH 4096
#define IW 4096
#define KH 9
#define KW 9
#define OH (IH - KH + 1)         // 4088
#define OW (IW - KW + 1)         // 4088

__global__ __launch_bounds__(TILE_X)
void conv9x9_kernel(const float* __restrict__ X,
                    const float* __restrict__ Kw,
                    const float* __restrict__ Bias,
                    float* __restrict__ Out)
{
    __shared__ float sX[SM_H][SM_W];
    __shared__ float sK[KH * KW];

    const int tid = threadIdx.x;
    const int x0  = blockIdx.x * TILE_X;
    const int y0  = blockIdx.y * OUT_Y;

    if (tid < KH * KW) sK[tid] = Kw[tid];

    // Cooperative tile load with boundary clamp (zeros outside; masked on store)
    #pragma unroll
    for (int idx = tid; idx < SM_H * SM_W; idx += TILE_X) {
        const int r = idx / SM_W;
        const int c = idx - r * SM_W;
        const int gy = y0 + r;
        const int gx = x0 + c;
        float v = 0.0f;
        if (gy < IH && gx < IW) v = X[(long)gy * IW + gx];
        sX[r][c] = v;
    }
    __syncthreads();

    const float bias = Bias[0];
    float acc[OUT_Y];
    #pragma unroll
    for (int i = 0; i < OUT_Y; i++) acc[i] = bias;

    #pragma unroll
    for (int kx = 0; kx < KW; kx++) {
        // weights for this kx column (smem broadcast)
        float w[KH];
        #pragma unroll
        for (int ky = 0; ky < KH; ky++) w[ky] = sK[ky * KW + kx];

        // column of input values covering the 16-output sliding window
        float v[SM_H];
        #pragma unroll
        for (int r = 0; r < SM_H; r++) v[r] = sX[r][tid + kx];

        #pragma unroll
        for (int ky = 0; ky < KH; ky++) {
            #pragma unroll
            for (int i = 0; i < OUT_Y; i++) {
                acc[i] = fmaf(w[ky], v[i + ky], acc[i]);
            }
        }
    }

    const int gx = x0 + tid;
    if (gx < OW) {
        #pragma unroll
        for (int i = 0; i < OUT_Y; i++) {
            const int gy = y0 + i;
            if (gy < OH) Out[(long)gy * OW + gx] = acc[i];
        }
    }
}

extern "C" void kernel_launch(void* const* d_in, const int* in_sizes, int n_in,
                              void* d_out, int out_size)
{
    const float* X    = (const float*)d_in[0];
    const float* Kw   = (const float*)d_in[1];
    const float* Bias = (const float*)d_in[2];
    float* Out        = (float*)d_out;

    dim3 grid((OW + TILE_X - 1) / TILE_X, (OH + OUT_Y - 1) / OUT_Y);
    dim3 block(TILE_X);
    conv9x9_kernel<<<grid, block>>>(X, Kw, Bias, Out);
}